// round 14
// baseline (speedup 1.0000x reference)
#include <cuda_runtime.h>
#include <cuda_fp16.h>
#include <math.h>

#define N_USER 20000
#define N_ITEM 20000
#define NTOT   40000
#define DD     128
#define HH     4
#define HD     512     // H*D
#define MM     8
#define TT     5
#define E_UI_  40000
#define E_T_   16000
#define NODE_SPLIT 24064        // 188 tiles on side stream; rest on main

// ---------------- scratch (device globals; no allocation allowed) ----------
__device__ __half   g_fc16[(size_t)2 * N_USER * HD];
__device__ __half   g_rst16[(size_t)2 * N_USER * HD];
__device__ float    g_el[2 * N_USER * HH];
__device__ float    g_er[2 * N_USER * HH];
__device__ float    g_trans[(size_t)NTOT * DD];
__device__ float    g_coef[(size_t)TT * E_T_ * MM];
__device__ float    g_ncoef[(size_t)NTOT * MM];
__device__ float    g_s[(size_t)NTOT * DD];
__device__ float    g_cnt[NTOT];
__device__ float    g_node[(size_t)NTOT * DD];
__device__ __half   g_feat16[(size_t)NTOT * DD];
__device__ float    g_emb1[(size_t)NTOT * DD];
__device__ float    g_emb2[(size_t)NTOT * DD];
// fp16 weights
__device__ __half   g_wfc[2 * 2 * HD * DD];
__device__ __half   g_wproj[2 * 2 * DD * HD];
__device__ __half   g_wrel[2 * TT * MM * DD * DD];
__device__ __half   g_wnode[2 * MM * DD * DD];
// attention projections
__device__ float    g_wal[2 * 2 * HH * DD];
__device__ float    g_war[2 * 2 * HH * DD];
// CSR
__device__ int      g_off_u[N_USER + 1];
__device__ int      g_off_i[N_ITEM + 1];
__device__ int      g_eid_u[E_UI_];
__device__ int      g_eid_i[E_UI_];
__device__ int      g_deg[N_USER];
__device__ int      g_cur[N_USER];

// ---------------- helpers ---------------------------------------------------
__device__ __forceinline__ float lrelu(float x) { return x > 0.f ? x : 0.2f * x; }
__device__ __forceinline__ float eluf(float x)  { return x > 0.f ? x : expm1f(x); }
__device__ __forceinline__ void mma16816(float* c, const unsigned* a, const unsigned* b) {
    asm volatile("mma.sync.aligned.m16n8k16.row.col.f32.f16.f16.f32 "
                 "{%0,%1,%2,%3},{%4,%5,%6,%7},{%8,%9},{%0,%1,%2,%3};"
                 : "+f"(c[0]), "+f"(c[1]), "+f"(c[2]), "+f"(c[3])
                 : "r"(a[0]), "r"(a[1]), "r"(a[2]), "r"(a[3]), "r"(b[0]), "r"(b[1]));
}
__device__ __forceinline__ void ldsm4(unsigned& r0, unsigned& r1, unsigned& r2, unsigned& r3,
                                      unsigned addr) {
    asm volatile("ldmatrix.sync.aligned.m8n8.x4.shared.b16 {%0,%1,%2,%3}, [%4];"
                 : "=r"(r0), "=r"(r1), "=r"(r2), "=r"(r3) : "r"(addr));
}
__device__ __forceinline__ void redv2(float* p, float a, float b) {
    asm volatile("red.global.add.v2.f32 [%0], {%1,%2};" :: "l"(p), "f"(a), "f"(b) : "memory");
}
__device__ __forceinline__ float warpsum(float v) {
#pragma unroll
    for (int o = 16; o; o >>= 1) v += __shfl_xor_sync(0xffffffffu, v, o);
    return v;
}
__device__ __forceinline__ float4 ldh4(const __half* p) {
    const __half2* q = (const __half2*)p;
    float2 a = __half22float2(q[0]);
    float2 b = __half22float2(q[1]);
    return make_float4(a.x, a.y, b.x, b.y);
}

// ---------------- weight convert to fp16 ------------------------------------
__global__ void round_all(const float* i0, __half* o0, int n0,
                          const float* i1, __half* o1, int n1,
                          const float* i2, __half* o2, int n2,
                          const float* i3, __half* o3, int n3)
{
    int stride = gridDim.x * blockDim.x;
    for (int i = blockIdx.x * blockDim.x + threadIdx.x; i < n0; i += stride)
        o0[i] = __float2half_rn(i0[i]);
    for (int i = blockIdx.x * blockDim.x + threadIdx.x; i < n1; i += stride)
        o1[i] = __float2half_rn(i1[i]);
    for (int i = blockIdx.x * blockDim.x + threadIdx.x; i < n2; i += stride)
        o2[i] = __float2half_rn(i2[i]);
    for (int i = blockIdx.x * blockDim.x + threadIdx.x; i < n3; i += stride)
        o3[i] = __float2half_rn(i3[i]);
}

__global__ void tohalf(const float* __restrict__ in, __half* __restrict__ out, int n)
{
    int i = blockIdx.x * blockDim.x + threadIdx.x;
    if (i < n) out[i] = __float2half_rn(in[i]);
}

// ---------------- wal = W^T al, war = W^T ar ---------------------------------
__global__ void walprep(const float* __restrict__ W, const float* __restrict__ al,
                        const float* __restrict__ ar,
                        float* __restrict__ wal, float* __restrict__ war)
{
    int h = blockIdx.x, g = blockIdx.y, k = threadIdx.x;
    float sl = 0.f, sr = 0.f;
    const float* wb = W + ((size_t)g * HD + h * DD) * DD + k;
    const float* alb = al + (g * HH + h) * DD;
    const float* arb = ar + (g * HH + h) * DD;
    for (int d = 0; d < DD; d++) {
        float wv = wb[(size_t)d * DD];
        sl += wv * alb[d];
        sr += wv * arb[d];
    }
    wal[(g * HH + h) * DD + k] = sl;
    war[(g * HH + h) * DD + k] = sr;
}

// ---------------- fused per-layer prep (reads fp16 feat) ---------------------
__global__ void prep_kernel(const __half* __restrict__ feat16,
                            const float* __restrict__ walL, const float* __restrict__ warL,
                            float* __restrict__ elb, float* __restrict__ erb,
                            const int* __restrict__ edge_dst,
                            const float* __restrict__ relWc, const float* __restrict__ relbc,
                            float* __restrict__ coef,
                            const float* __restrict__ nodeWc, const float* __restrict__ nodebc,
                            float* __restrict__ ncoef)
{
    int w = (blockIdx.x * blockDim.x + threadIdx.x) >> 5;
    int lane = threadIdx.x & 31;
    if (w < 2 * 2 * N_USER) {
        int side = w / (2 * N_USER);
        int u = w - side * 2 * N_USER;
        int isEr = u >= N_USER;
        int i = u - (isEr ? N_USER : 0);
        int n = (side == 0) ? (isEr ? i : N_USER + i) : (isEr ? N_USER + i : i);
        float4 f = ldh4(feat16 + (long long)n * DD + lane * 4);
        const float* wb = (isEr ? warL : walL) + side * HH * DD;
        float* ob = (isEr ? erb : elb) + side * N_USER * HH + i * HH;
#pragma unroll
        for (int h = 0; h < HH; h++) {
            float4 a = ((const float4*)(wb + h * DD))[lane];
            float s = f.x * a.x + f.y * a.y + f.z * a.z + f.w * a.w;
#pragma unroll
            for (int o = 16; o; o >>= 1) s += __shfl_down_sync(0xffffffffu, s, o);
            if (lane == 0) ob[h] = s;
        }
    } else if (w < 2 * 2 * N_USER + TT * E_T_) {
        int warp = w - 2 * 2 * N_USER;
        int t = warp / E_T_;
        int d = edge_dst[warp];
        float4 hv = ldh4(feat16 + (long long)d * DD + lane * 4);
#pragma unroll
        for (int m = 0; m < MM; m++) {
            float4 ww = ((const float4*)(relWc + ((long long)t * MM + m) * DD))[lane];
            float s = hv.x * ww.x + hv.y * ww.y + hv.z * ww.z + hv.w * ww.w;
#pragma unroll
            for (int o = 16; o; o >>= 1) s += __shfl_down_sync(0xffffffffu, s, o);
            if (lane == 0) coef[(long long)warp * MM + m] = lrelu(s + relbc[t * MM + m]);
        }
    } else if (w < 2 * 2 * N_USER + TT * E_T_ + NTOT) {
        int warp = w - (2 * 2 * N_USER + TT * E_T_);
        float4 hv = ldh4(feat16 + (long long)warp * DD + lane * 4);
#pragma unroll
        for (int m = 0; m < MM; m++) {
            float4 ww = ((const float4*)(nodeWc + (long long)m * DD))[lane];
            float s = hv.x * ww.x + hv.y * ww.y + hv.z * ww.z + hv.w * ww.w;
#pragma unroll
            for (int o = 16; o; o >>= 1) s += __shfl_down_sync(0xffffffffu, s, o);
            if (lane == 0) ncoef[(long long)warp * MM + m] = lrelu(s + nodebc[m]);
        }
    }
}
#define PREP_WARPS (2 * 2 * N_USER + TT * E_T_ + NTOT)   // 200000

// ---------------- CSR build --------------------------------------------------
__global__ void hist_kernel(const int* __restrict__ dst, int* __restrict__ deg, int n)
{
    int i = blockIdx.x * blockDim.x + threadIdx.x;
    if (i < n) atomicAdd(&deg[dst[i]], 1);
}

__global__ void scan_fast(const int* __restrict__ deg, int* __restrict__ off, int n)
{
    __shared__ int wsum[32];
    int tid  = threadIdx.x;
    int lane = tid & 31, w = tid >> 5;
    int C = (n + 1023) >> 10;
    int start = tid * C;
    int end = min(start + C, n);
    int total = 0;
    for (int i = start; i < end; i++) total += deg[i];
    int incl = total;
#pragma unroll
    for (int o = 1; o < 32; o <<= 1) {
        int v = __shfl_up_sync(0xffffffffu, incl, o);
        if (lane >= o) incl += v;
    }
    if (lane == 31) wsum[w] = incl;
    __syncthreads();
    if (w == 0) {
        int v = wsum[lane];
        int iv = v;
#pragma unroll
        for (int o = 1; o < 32; o <<= 1) {
            int u = __shfl_up_sync(0xffffffffu, iv, o);
            if (lane >= o) iv += u;
        }
        wsum[lane] = iv - v;
    }
    __syncthreads();
    int run = wsum[w] + incl - total;
    for (int i = start; i < end; i++) {
        run += deg[i];
        off[i + 1] = run;
    }
    if (tid == 0) off[0] = 0;
}

__global__ void fill_csr(const int* __restrict__ dst, int* __restrict__ cur,
                         int* __restrict__ eid, int n)
{
    int i = blockIdx.x * blockDim.x + threadIdx.x;
    if (i < n) {
        int pos = atomicAdd(&cur[dst[i]], 1);
        eid[pos] = i;
    }
}

// ---------------- fp16 tensor-core GEMM (BK=64, ldmatrix, dual-cfg, splitK) --
#define BK 64
#define LDT 72
#define TILEH (128 * LDT)
#define SMB (2 * 2 * TILEH * 2 + 1024 * 4)

struct GemmCfg {
    const __half* A; const int* gidx; const float* coef;
    const __half* B; int bSeg; long long bStride; long long bTStride;
    float* C; __half* Ch; const int* sidx; const float* bias; int biasTS; int act;
    int aOff0, aOff1; long long cTStride;
    int Mrows, K, aSeg, ldc, tilesPerT, kSplit;
};

__global__ __launch_bounds__(256, 2)
void gemm_fp16(GemmCfg c0, GemmCfg c1, int splitY)
{
    const bool first = (int)blockIdx.y < splitY;
    const GemmCfg c = first ? c0 : c1;
    const int by = first ? blockIdx.y : blockIdx.y - splitY;

    extern __shared__ __half smh[];
    float* sCoef = (float*)(smh + 4 * TILEH);

    const int tid  = threadIdx.x;
    const int lane = tid & 31, wid = tid >> 5;
    const int warpM = wid & 3, warpN = wid >> 2;
    const int t    = by / c.tilesPerT;
    const int row0 = (by % c.tilesPerT) * 128;
    const bool ksp = c.kSplit > 1;
    const int kLen = c.K / c.kSplit;
    const int kBase = ksp ? (int)blockIdx.x * kLen : 0;
    const int col0 = ksp ? 0 : blockIdx.x * 128;
    const int aOff = t ? c.aOff1 : c.aOff0;

    const int lrow = tid >> 1;
    const int lcol = (tid & 1) * 32;
    const int growL  = row0 + lrow;
    const bool rowokL = growL < c.Mrows;
    const int arowL  = (rowokL ? (c.gidx ? c.gidx[(long long)t * c.Mrows + growL] : growL) : 0) + aOff;
    const __half* AbaseL = c.A + (long long)arowL * c.aSeg + lcol;
    const __half* BbaseL = c.B + t * c.bTStride + (long long)(col0 + lrow) * c.bSeg + lcol;
    const int aBytes = rowokL ? 16 : 0;

    if (c.coef) {
        for (int i = tid; i < 1024; i += 256) {
            int r = i >> 3, m = i & 7;
            int gr = row0 + r;
            sCoef[i] = (gr < c.Mrows) ? c.coef[((long long)t * c.Mrows + gr) * 8 + m] : 0.f;
        }
    }

    const unsigned smBase = (unsigned)__cvta_generic_to_shared(smh);
    unsigned aoffB[2];
#pragma unroll
    for (int mt = 0; mt < 2; mt++) {
        int ar = warpM * 32 + mt * 16 + (lane & 15);
        int ak = (lane >> 4) << 3;
        aoffB[mt] = (unsigned)(ar * LDT + ak) * 2;
    }
    unsigned boffB[4];
#pragma unroll
    for (int p = 0; p < 4; p++) {
        int nr = warpN * 64 + (p * 2 + (lane >> 4)) * 8 + (lane & 7);
        int nk = ((lane >> 3) & 1) << 3;
        boffB[p] = (unsigned)(nr * LDT + nk) * 2 + (unsigned)TILEH * 2;
    }

    float acc[2][8][4];
#pragma unroll
    for (int i = 0; i < 2; i++)
#pragma unroll
        for (int j = 0; j < 8; j++)
#pragma unroll
            for (int q = 0; q < 4; q++) acc[i][j][q] = 0.f;

    const int ntiles = kLen / BK;

    auto loadTile = [&](int kt, int b) {
        int kg = kBase + kt * BK;
        const __half* ga = AbaseL + kg % c.aSeg;
        const __half* gb = BbaseL + (long long)(kg / c.bSeg) * c.bStride + kg % c.bSeg;
        unsigned da = (unsigned)__cvta_generic_to_shared(smh + b * 2 * TILEH + lrow * LDT + lcol);
        unsigned db = (unsigned)__cvta_generic_to_shared(smh + b * 2 * TILEH + TILEH + lrow * LDT + lcol);
#pragma unroll
        for (int j = 0; j < 4; j++) {
            asm volatile("cp.async.ca.shared.global [%0], [%1], 16, %2;"
                         :: "r"(da + j * 16), "l"(ga + j * 8), "r"(aBytes));
            asm volatile("cp.async.ca.shared.global [%0], [%1], 16;"
                         :: "r"(db + j * 16), "l"(gb + j * 8));
        }
    };

    loadTile(0, 0);
    asm volatile("cp.async.commit_group;");
    int buf = 0;
    for (int kt = 0; kt < ntiles; kt++) {
        asm volatile("cp.async.wait_group 0;");
        __syncthreads();
        if (kt + 1 < ntiles) {
            loadTile(kt + 1, buf ^ 1);
            asm volatile("cp.async.commit_group;");
        }

        const unsigned tileB = smBase + (unsigned)(buf * 2 * TILEH) * 2;
        __half2 cf2[2][2];
        if (c.coef) {
            int seg = (kBase + kt * BK) / c.aSeg;
#pragma unroll
            for (int mt = 0; mt < 2; mt++) {
                int rr = warpM * 32 + mt * 16 + (lane >> 2);
                cf2[mt][0] = __float2half2_rn(sCoef[rr * 8 + seg]);
                cf2[mt][1] = __float2half2_rn(sCoef[(rr + 8) * 8 + seg]);
            }
        }
#pragma unroll
        for (int kk = 0; kk < BK; kk += 16) {
            unsigned af[2][4], bf[8][2];
#pragma unroll
            for (int mt = 0; mt < 2; mt++) {
                ldsm4(af[mt][0], af[mt][1], af[mt][2], af[mt][3],
                      tileB + aoffB[mt] + kk * 2);
                if (c.coef) {
                    __half2* a2 = (__half2*)af[mt];
                    a2[0] = __hmul2(a2[0], cf2[mt][0]);
                    a2[1] = __hmul2(a2[1], cf2[mt][1]);
                    a2[2] = __hmul2(a2[2], cf2[mt][0]);
                    a2[3] = __hmul2(a2[3], cf2[mt][1]);
                }
            }
#pragma unroll
            for (int p = 0; p < 4; p++) {
                ldsm4(bf[2 * p][0], bf[2 * p][1], bf[2 * p + 1][0], bf[2 * p + 1][1],
                      tileB + boffB[p] + kk * 2);
            }
#pragma unroll
            for (int mt = 0; mt < 2; mt++)
#pragma unroll
                for (int nt = 0; nt < 8; nt++)
                    mma16816(acc[mt][nt], af[mt], bf[nt]);
        }
        buf ^= 1;
    }

    // epilogue
#pragma unroll
    for (int mt = 0; mt < 2; mt++)
#pragma unroll
        for (int h = 0; h < 2; h++) {
            int r = row0 + warpM * 32 + mt * 16 + (lane >> 2) + 8 * h;
            if (r >= c.Mrows) continue;
            if (c.sidx) {
                long long orow = c.sidx[(long long)t * c.Mrows + r];
                long long base = orow * c.ldc + col0;
#pragma unroll
                for (int nt = 0; nt < 8; nt++) {
                    int cc = warpN * 64 + nt * 8 + 2 * (lane & 3);
                    redv2(&c.C[base + cc], acc[mt][nt][2 * h], acc[mt][nt][2 * h + 1]);
                }
            } else if (ksp) {
                long long base = (long long)t * c.cTStride + (long long)r * c.ldc + col0;
#pragma unroll
                for (int nt = 0; nt < 8; nt++) {
                    int cc = warpN * 64 + nt * 8 + 2 * (lane & 3);
                    redv2(&c.C[base + cc], acc[mt][nt][2 * h], acc[mt][nt][2 * h + 1]);
                }
            } else {
                long long base = (long long)t * c.cTStride + (long long)r * c.ldc + col0;
#pragma unroll
                for (int nt = 0; nt < 8; nt++) {
                    int cc = warpN * 64 + nt * 8 + 2 * (lane & 3);
                    float v0 = acc[mt][nt][2 * h];
                    float v1 = acc[mt][nt][2 * h + 1];
                    if (c.bias) {
                        v0 += c.bias[t * c.biasTS + col0 + cc];
                        v1 += c.bias[t * c.biasTS + col0 + cc + 1];
                    }
                    if (c.act == 1) { v0 = eluf(v0); v1 = eluf(v1); }
                    if (c.Ch) {
                        *(__half2*)&c.Ch[base + cc] = __floats2half2_rn(v0, v1);
                    } else {
                        float2 v = make_float2(v0, v1);
                        *(float2*)&c.C[base + cc] = v;
                    }
                }
            }
        }
}

// ---------------- fused CSR GAT (both sides, one launch; fp16 fc gather) -----
__global__ void gat_agg2(const int* __restrict__ off_u, const int* __restrict__ eid_u,
                         const int* __restrict__ off_i, const int* __restrict__ eid_i,
                         const int* __restrict__ dst_i, const int* __restrict__ src_u,
                         const float* __restrict__ elb, const float* __restrict__ erb,
                         const __half* __restrict__ fcb, const float* __restrict__ biasb,
                         __half* __restrict__ rstb)
{
    int w = (blockIdx.x * blockDim.x + threadIdx.x) >> 5;
    int lane = threadIdx.x & 31;
    if (w >= 2 * N_USER * HH) return;
    int side = w >= N_USER * HH;
    int wl = w - side * N_USER * HH;
    int node = wl >> 2, h = wl & 3;
    const int* off  = side ? off_i : off_u;
    const int* eid  = side ? eid_i : eid_u;
    const int* sIdx = side ? src_u : dst_i;
    const float* el = elb + side * N_USER * HH;
    float erd = (erb + side * N_USER * HH)[node * HH + h];
    const __half* fc = fcb + (size_t)side * N_USER * HD;
    const float* bias = biasb + side * HD;
    __half* rst = rstb + (size_t)side * N_USER * HD;

    int o0 = off[node], o1 = off[node + 1];

    float m = -1e30f;
    for (int j = o0 + lane; j < o1; j += 32) {
        int s = sIdx[eid[j]];
        m = fmaxf(m, lrelu(el[s * HH + h] + erd));
    }
#pragma unroll
    for (int o = 16; o; o >>= 1) m = fmaxf(m, __shfl_xor_sync(0xffffffffu, m, o));

    float4 acc = make_float4(0.f, 0.f, 0.f, 0.f);
    float den = 0.f;
    for (int j = o0; j < o1; j++) {
        int s = sIdx[eid[j]];
        float ex = expf(lrelu(el[s * HH + h] + erd) - m);
        den += ex;
        const __half2* fp = (const __half2*)(fc + (long long)s * HD + h * DD + lane * 4);
        float2 fa = __half22float2(fp[0]);
        float2 fb = __half22float2(fp[1]);
        acc.x += ex * fa.x; acc.y += ex * fa.y; acc.z += ex * fb.x; acc.w += ex * fb.y;
    }
    float inv = (o1 > o0) ? 1.f / den : 0.f;
    float4 b = ((const float4*)(bias + h * DD))[lane];
    __half2 h0 = __floats2half2_rn(eluf(acc.x * inv + b.x), eluf(acc.y * inv + b.y));
    __half2 h1 = __floats2half2_rn(eluf(acc.z * inv + b.z), eluf(acc.w * inv + b.w));
    __half2* dst = (__half2*)(rst + (long long)node * HD + h * DD + lane * 4);
    dst[0] = h0; dst[1] = h1;
}

__global__ void cnt_kernel(const int* __restrict__ edge_dst, float* __restrict__ cnt)
{
    int i = blockIdx.x * blockDim.x + threadIdx.x;
    if (i >= TT * E_T_) return;
    atomicAdd(&cnt[edge_dst[i]], 1.f);
}

// ---------------- combine (warp per node; proj bias+elu folded in) -----------
__global__ void combine_kernel(const float* __restrict__ s, const float* __restrict__ cnt,
                               const float* __restrict__ lnw, const float* __restrict__ lnb,
                               const float* __restrict__ hbias,
                               const float* __restrict__ node, const float* __restrict__ trans,
                               const float* __restrict__ projb,
                               __half* __restrict__ featOut16,
                               float* __restrict__ embOut)
{
    int w = (blockIdx.x * blockDim.x + threadIdx.x) >> 5;
    int lane = threadIdx.x & 31;
    if (w >= NTOT) return;
    int n = w;
    float inv = 1.f / fmaxf(cnt[n], 1.f);
    float4 sv = ((const float4*)(s + (long long)n * DD))[lane];
    float4 agg = make_float4(sv.x * inv, sv.y * inv, sv.z * inv, sv.w * inv);
    float mean = warpsum(agg.x + agg.y + agg.z + agg.w) * (1.f / DD);
    float4 df = make_float4(agg.x - mean, agg.y - mean, agg.z - mean, agg.w - mean);
    float var = warpsum(df.x * df.x + df.y * df.y + df.z * df.z + df.w * df.w) * (1.f / DD);
    float rs = rsqrtf(var + 1e-5f);
    float4 wv = ((const float4*)lnw)[lane];
    float4 bv = ((const float4*)lnb)[lane];
    float4 hv = ((const float4*)hbias)[lane];
    float4 nv = ((const float4*)(node + (long long)n * DD))[lane];
    float4 tv = ((const float4*)(trans + (long long)n * DD))[lane];
    int side = n >= N_USER;
    float4 pb = ((const float4*)(projb + side * DD))[lane];
    float4 f;
    f.x = lrelu(df.x * rs * wv.x + bv.x + hv.x + nv.x) + eluf(tv.x + pb.x);
    f.y = lrelu(df.y * rs * wv.y + bv.y + hv.y + nv.y) + eluf(tv.y + pb.y);
    f.z = lrelu(df.z * rs * wv.z + bv.z + hv.z + nv.z) + eluf(tv.z + pb.z);
    f.w = lrelu(df.w * rs * wv.w + bv.w + hv.w + nv.w) + eluf(tv.w + pb.w);
    __half2* f16 = (__half2*)(featOut16 + (long long)n * DD + lane * 4);
    f16[0] = __floats2half2_rn(f.x, f.y);
    f16[1] = __floats2half2_rn(f.z, f.w);
    ((float4*)(embOut + (long long)n * DD))[lane] = f;
}

// ---------------- final layernorm (warp per node) ----------------------------
__global__ void final_kernel(const float* __restrict__ emb0,
                             const float* __restrict__ e1, const float* __restrict__ e2,
                             const float* __restrict__ w, const float* __restrict__ b,
                             float* __restrict__ out)
{
    int wp = (blockIdx.x * blockDim.x + threadIdx.x) >> 5;
    int lane = threadIdx.x & 31;
    if (wp >= NTOT) return;
    int n = wp;
    float4 x0 = ((const float4*)(emb0 + (long long)n * DD))[lane];
    float4 x1 = ((const float4*)(e1 + (long long)n * DD))[lane];
    float4 x2 = ((const float4*)(e2 + (long long)n * DD))[lane];
    float mean = warpsum(x0.x + x0.y + x0.z + x0.w + x1.x + x1.y + x1.z + x1.w
                       + x2.x + x2.y + x2.z + x2.w) * (1.f / 384.f);
    float4 d0 = make_float4(x0.x - mean, x0.y - mean, x0.z - mean, x0.w - mean);
    float4 d1 = make_float4(x1.x - mean, x1.y - mean, x1.z - mean, x1.w - mean);
    float4 d2 = make_float4(x2.x - mean, x2.y - mean, x2.z - mean, x2.w - mean);
    float var = warpsum(d0.x * d0.x + d0.y * d0.y + d0.z * d0.z + d0.w * d0.w
                      + d1.x * d1.x + d1.y * d1.y + d1.z * d1.z + d1.w * d1.w
                      + d2.x * d2.x + d2.y * d2.y + d2.z * d2.z + d2.w * d2.w) * (1.f / 384.f);
    float rs = rsqrtf(var + 1e-5f);
    long long base = (long long)n * 384;
    float4 w0 = ((const float4*)w)[lane];
    float4 w1 = ((const float4*)(w + 128))[lane];
    float4 w2 = ((const float4*)(w + 256))[lane];
    float4 b0 = ((const float4*)b)[lane];
    float4 b1 = ((const float4*)(b + 128))[lane];
    float4 b2 = ((const float4*)(b + 256))[lane];
    float4 o0 = make_float4(d0.x * rs * w0.x + b0.x, d0.y * rs * w0.y + b0.y,
                            d0.z * rs * w0.z + b0.z, d0.w * rs * w0.w + b0.w);
    float4 o1 = make_float4(d1.x * rs * w1.x + b1.x, d1.y * rs * w1.y + b1.y,
                            d1.z * rs * w1.z + b1.z, d1.w * rs * w1.w + b1.w);
    float4 o2 = make_float4(d2.x * rs * w2.x + b2.x, d2.y * rs * w2.y + b2.y,
                            d2.z * rs * w2.z + b2.z, d2.w * rs * w2.w + b2.w);
    ((float4*)(out + base))[lane]       = o0;
    ((float4*)(out + base + 128))[lane] = o1;
    ((float4*)(out + base + 256))[lane] = o2;
}

// ---------------- host driver ------------------------------------------------
extern "C" void kernel_launch(void* const* d_in, const int* in_sizes, int n_in,
                              void* d_out, int out_size)
{
    const float* embedding = (const float*)d_in[0];
    const float* gat_fc_W  = (const float*)d_in[1];
    const float* gat_al    = (const float*)d_in[2];
    const float* gat_ar    = (const float*)d_in[3];
    const float* gat_bias  = (const float*)d_in[4];
    const float* proj_W    = (const float*)d_in[5];
    const float* proj_b    = (const float*)d_in[6];
    const float* rel_Wc    = (const float*)d_in[7];
    const float* rel_bc    = (const float*)d_in[8];
    const float* rel_Ww    = (const float*)d_in[9];
    const float* node_Wc   = (const float*)d_in[10];
    const float* node_bc   = (const float*)d_in[11];
    const float* node_Ww   = (const float*)d_in[12];
    const float* h_bias    = (const float*)d_in[13];
    const float* ln_w      = (const float*)d_in[14];
    const float* ln_b      = (const float*)d_in[15];
    const float* fln_w     = (const float*)d_in[16];
    const float* fln_b     = (const float*)d_in[17];
    const int*   src_u     = (const int*)d_in[18];
    const int*   dst_i     = (const int*)d_in[19];
    const int*   edge_src  = (const int*)d_in[20];
    const int*   edge_dst  = (const int*)d_in[21];
    float* out = (float*)d_out;

    float *p_el, *p_er, *p_trans, *p_coef,
          *p_ncoef, *p_s, *p_cnt, *p_node, *p_e1, *p_e2,
          *p_wal, *p_war;
    __half *p_fc16, *p_feat16, *p_rst16, *p_wfc, *p_wproj, *p_wrel, *p_wnode;
    int *p_off_u, *p_off_i, *p_eid_u, *p_eid_i, *p_deg, *p_cur;
    cudaGetSymbolAddress((void**)&p_fc16, g_fc16);
    cudaGetSymbolAddress((void**)&p_rst16, g_rst16);
    cudaGetSymbolAddress((void**)&p_el, g_el);
    cudaGetSymbolAddress((void**)&p_er, g_er);
    cudaGetSymbolAddress((void**)&p_trans, g_trans);
    cudaGetSymbolAddress((void**)&p_coef, g_coef);
    cudaGetSymbolAddress((void**)&p_ncoef, g_ncoef);
    cudaGetSymbolAddress((void**)&p_s, g_s);
    cudaGetSymbolAddress((void**)&p_cnt, g_cnt);
    cudaGetSymbolAddress((void**)&p_node, g_node);
    cudaGetSymbolAddress((void**)&p_feat16, g_feat16);
    cudaGetSymbolAddress((void**)&p_e1, g_emb1);
    cudaGetSymbolAddress((void**)&p_e2, g_emb2);
    cudaGetSymbolAddress((void**)&p_wfc, g_wfc);
    cudaGetSymbolAddress((void**)&p_wproj, g_wproj);
    cudaGetSymbolAddress((void**)&p_wrel, g_wrel);
    cudaGetSymbolAddress((void**)&p_wnode, g_wnode);
    cudaGetSymbolAddress((void**)&p_wal, g_wal);
    cudaGetSymbolAddress((void**)&p_war, g_war);
    cudaGetSymbolAddress((void**)&p_off_u, g_off_u);
    cudaGetSymbolAddress((void**)&p_off_i, g_off_i);
    cudaGetSymbolAddress((void**)&p_eid_u, g_eid_u);
    cudaGetSymbolAddress((void**)&p_eid_i, g_eid_i);
    cudaGetSymbolAddress((void**)&p_deg, g_deg);
    cudaGetSymbolAddress((void**)&p_cur, g_cur);

    cudaFuncSetAttribute(gemm_fp16, cudaFuncAttributeMaxDynamicSharedMemorySize, SMB);

    auto mkCfg = [](const __half* A, const int* gidx, const float* coefp,
                    const __half* B, int bSeg, long long bStride, long long bTStride,
                    float* C, __half* Ch, const int* sidx,
                    const float* bias, int biasTS, int act,
                    int aOff0, int aOff1, long long cTStride,
                    int M, int K, int aSeg, int ldc, int tilesPerT, int kSplit) {
        GemmCfg c;
        c.A = A; c.gidx = gidx; c.coef = coefp;
        c.B = B; c.bSeg = bSeg; c.bStride = bStride; c.bTStride = bTStride;
        c.C = C; c.Ch = Ch; c.sidx = sidx; c.bias = bias; c.biasTS = biasTS; c.act = act;
        c.aOff0 = aOff0; c.aOff1 = aOff1; c.cTStride = cTStride;
        c.Mrows = M; c.K = K; c.aSeg = aSeg; c.ldc = ldc; c.tilesPerT = tilesPerT;
        c.kSplit = kSplit;
        return c;
    };

    // ---- side stream + events (per call; capture-safe; leaked) ----
    cudaStream_t sB;
    cudaStreamCreateWithFlags(&sB, cudaStreamNonBlocking);
    cudaEvent_t eFork, eCSR, eComb[2], ePrep[2], eMem[2];
    cudaEventCreateWithFlags(&eFork, cudaEventDisableTiming);
    cudaEventCreateWithFlags(&eCSR,  cudaEventDisableTiming);
    for (int l = 0; l < 2; l++) {
        cudaEventCreateWithFlags(&eComb[l], cudaEventDisableTiming);
        cudaEventCreateWithFlags(&ePrep[l], cudaEventDisableTiming);
        cudaEventCreateWithFlags(&eMem[l],  cudaEventDisableTiming);
    }

    cudaEventRecord(eFork, 0);
    cudaStreamWaitEvent(sB, eFork, 0);

    cudaMemsetAsync(p_cnt, 0, NTOT * 4, sB);
    cnt_kernel<<<(TT * E_T_ + 255) / 256, 256, 0, sB>>>(edge_dst, p_cnt);
    cudaMemsetAsync(p_deg, 0, N_USER * 4, sB);
    hist_kernel<<<(E_UI_ + 255) / 256, 256, 0, sB>>>(src_u, p_deg, E_UI_);
    scan_fast<<<1, 1024, 0, sB>>>(p_deg, p_off_u, N_USER);
    cudaMemcpyAsync(p_cur, p_off_u, N_USER * 4, cudaMemcpyDeviceToDevice, sB);
    fill_csr<<<(E_UI_ + 255) / 256, 256, 0, sB>>>(src_u, p_cur, p_eid_u, E_UI_);
    cudaMemsetAsync(p_deg, 0, N_ITEM * 4, sB);
    hist_kernel<<<(E_UI_ + 255) / 256, 256, 0, sB>>>(dst_i, p_deg, E_UI_);
    scan_fast<<<1, 1024, 0, sB>>>(p_deg, p_off_i, N_ITEM);
    cudaMemcpyAsync(p_cur, p_off_i, N_ITEM * 4, cudaMemcpyDeviceToDevice, sB);
    fill_csr<<<(E_UI_ + 255) / 256, 256, 0, sB>>>(dst_i, p_cur, p_eid_i, E_UI_);
    cudaEventRecord(eCSR, sB);

    round_all<<<512, 256>>>(gat_fc_W, p_wfc, 2*2*HD*DD,
                            proj_W, p_wproj, 2*2*DD*HD,
                            rel_Ww, p_wrel, 2*TT*MM*DD*DD,
                            node_Ww, p_wnode, 2*MM*DD*DD);
    walprep<<<dim3(HH, 4), DD>>>(gat_fc_W, gat_al, gat_ar, p_wal, p_war);
    tohalf<<<(NTOT * DD + 255) / 256, 256>>>(embedding, p_feat16, NTOT * DD);
    cudaEventRecord(eComb[0], 0);

    for (int l = 0; l < 2; l++) {
        // side chain: prep -> memset s -> rel + node[0:NODE_SPLIT) gemm
        cudaStreamWaitEvent(sB, eComb[l], 0);
        prep_kernel<<<(PREP_WARPS * 32 + 255) / 256, 256, 0, sB>>>(
            p_feat16, p_wal + (size_t)l * 2 * HH * DD, p_war + (size_t)l * 2 * HH * DD,
            p_el, p_er,
            edge_dst, rel_Wc + (size_t)l * TT * MM * DD, rel_bc + (size_t)l * TT * MM, p_coef,
            node_Wc + (size_t)l * MM * DD, node_bc + (size_t)l * MM, p_ncoef);
        cudaEventRecord(ePrep[l], sB);
        cudaMemsetAsync(p_s, 0, (size_t)NTOT * DD * 4, sB);
        {
            GemmCfg cr = mkCfg(p_feat16, edge_src, p_coef,
                               p_wrel + (size_t)l * TT * MM * DD * DD, DD,
                               (long long)DD * DD, (long long)MM * DD * DD,
                               p_s, nullptr, edge_dst, nullptr, 0, 0,
                               0, 0, 0,
                               E_T_, MM * DD, DD, DD, 125, 1);
            GemmCfg cn = mkCfg(p_feat16, nullptr, p_ncoef,
                               p_wnode + (size_t)l * MM * DD * DD, DD,
                               (long long)DD * DD, 0,
                               p_node, nullptr, nullptr, nullptr, 0, 0,
                               0, 0, 0,
                               NODE_SPLIT, MM * DD, DD, DD, NODE_SPLIT / 128, 1);
            int splitY = TT * 125;
            dim3 g(1, splitY + NODE_SPLIT / 128);
            gemm_fp16<<<g, 256, SMB, sB>>>(cr, cn, splitY);
        }
        cudaEventRecord(eMem[l], sB);

        // main chain: fc gemm -> gat -> proj(splitK) -> node[NODE_SPLIT:) gemm
        {
            GemmCfg cf = mkCfg(p_feat16, nullptr, nullptr,
                               p_wfc + (size_t)l * 2 * HD * DD, DD, 0, (long long)HD * DD,
                               nullptr, p_fc16, nullptr, nullptr, 0, 0,
                               N_USER, 0, (long long)N_USER * HD,
                               N_USER, DD, DD, HD, 157, 1);
            dim3 g(HD / 128, 157 * 2);
            gemm_fp16<<<g, 256, SMB>>>(cf, cf, 1 << 30);
        }
        cudaMemsetAsync(p_trans, 0, (size_t)NTOT * DD * 4);
        if (l == 0) cudaStreamWaitEvent(0, eCSR, 0);
        cudaStreamWaitEvent(0, ePrep[l], 0);
        gat_agg2<<<(2 * N_USER * HH * 32 + 255) / 256, 256>>>(
            p_off_u, p_eid_u, p_off_i, p_eid_i, dst_i, src_u,
            p_el, p_er, p_fc16, gat_bias + (size_t)l * 2 * HD, p_rst16);
        {
            GemmCfg cp = mkCfg(p_rst16, nullptr, nullptr,
                               p_wproj + (size_t)l * 2 * DD * HD, HD, 0, (long long)DD * HD,
                               p_trans, nullptr, nullptr,
                               nullptr, 0, 0,
                               0, N_USER, (long long)N_USER * DD,
                               N_USER, HD, HD, DD, 157, 2);
            dim3 g(2, 157 * 2);
            gemm_fp16<<<g, 256, SMB>>>(cp, cp, 1 << 30);
        }
        {
            // node rows [NODE_SPLIT, NTOT) on main stream
            int Mrem = NTOT - NODE_SPLIT;                 // 15936
            int tiles = (Mrem + 127) / 128;               // 125
            GemmCfg cn2 = mkCfg(p_feat16, nullptr, p_ncoef + (size_t)NODE_SPLIT * MM,
                                p_wnode + (size_t)l * MM * DD * DD, DD,
                                (long long)DD * DD, 0,
                                p_node + (size_t)NODE_SPLIT * DD, nullptr, nullptr,
                                nullptr, 0, 0,
                                NODE_SPLIT, 0, 0,
                                Mrem, MM * DD, DD, DD, tiles, 1);
            dim3 g(1, tiles);
            gemm_fp16<<<g, 256, SMB>>>(cn2, cn2, 1 << 30);
        }

        cudaStreamWaitEvent(0, eMem[l], 0);
        combine_kernel<<<(NTOT * 32 + 255) / 256, 256>>>(
            p_s, p_cnt, ln_w + (size_t)l * DD, ln_b + (size_t)l * DD,
            h_bias + (size_t)l * DD, p_node, p_trans,
            proj_b + (size_t)l * 2 * DD,
            p_feat16, l == 0 ? p_e1 : p_e2);
        if (l == 0) cudaEventRecord(eComb[1], 0);
    }
    final_kernel<<<(NTOT * 32 + 255) / 256, 256>>>(embedding, p_e1, p_e2, fln_w, fln_b, out);
    (void)in_sizes; (void)n_in; (void)out_size;
}

// round 15
// speedup vs baseline: 1.0243x; 1.0243x over previous
#include <cuda_runtime.h>
#include <cuda_fp16.h>
#include <math.h>

#define N_USER 20000
#define N_ITEM 20000
#define NTOT   40000
#define DD     128
#define HH     4
#define HD     512     // H*D
#define MM     8
#define TT     5
#define E_UI_  40000
#define E_T_   16000

// ---------------- scratch (device globals; no allocation allowed) ----------
__device__ __half   g_fc16[(size_t)2 * N_USER * HD];
__device__ __half   g_rst16[(size_t)2 * N_USER * HD];
__device__ float    g_el[2 * N_USER * HH];
__device__ float    g_er[2 * N_USER * HH];
__device__ float    g_trans[(size_t)NTOT * DD];
__device__ float    g_coef[(size_t)TT * E_T_ * MM];
__device__ float    g_ncoef[(size_t)NTOT * MM];
__device__ float    g_s[(size_t)NTOT * DD];
__device__ float    g_cnt[NTOT];
__device__ float    g_node[(size_t)NTOT * DD];
__device__ __half   g_feat16[(size_t)NTOT * DD];
__device__ float    g_emb1[(size_t)NTOT * DD];
__device__ float    g_emb2[(size_t)NTOT * DD];
// fp16 weights
__device__ __half   g_wfc[2 * 2 * HD * DD];
__device__ __half   g_wproj[2 * 2 * DD * HD];
__device__ __half   g_wrel[2 * TT * MM * DD * DD];
__device__ __half   g_wnode[2 * MM * DD * DD];
// attention projections
__device__ float    g_wal[2 * 2 * HH * DD];
__device__ float    g_war[2 * 2 * HH * DD];
// CSR
__device__ int      g_off_u[N_USER + 1];
__device__ int      g_off_i[N_ITEM + 1];
__device__ int      g_eid_u[E_UI_];
__device__ int      g_eid_i[E_UI_];
__device__ int      g_deg[N_USER];
__device__ int      g_cur[N_USER];

// ---------------- helpers ---------------------------------------------------
__device__ __forceinline__ float lrelu(float x) { return x > 0.f ? x : 0.2f * x; }
__device__ __forceinline__ float eluf(float x)  { return x > 0.f ? x : expm1f(x); }
__device__ __forceinline__ void mma16816(float* c, const unsigned* a, const unsigned* b) {
    asm volatile("mma.sync.aligned.m16n8k16.row.col.f32.f16.f16.f32 "
                 "{%0,%1,%2,%3},{%4,%5,%6,%7},{%8,%9},{%0,%1,%2,%3};"
                 : "+f"(c[0]), "+f"(c[1]), "+f"(c[2]), "+f"(c[3])
                 : "r"(a[0]), "r"(a[1]), "r"(a[2]), "r"(a[3]), "r"(b[0]), "r"(b[1]));
}
__device__ __forceinline__ void ldsm4(unsigned& r0, unsigned& r1, unsigned& r2, unsigned& r3,
                                      unsigned addr) {
    asm volatile("ldmatrix.sync.aligned.m8n8.x4.shared.b16 {%0,%1,%2,%3}, [%4];"
                 : "=r"(r0), "=r"(r1), "=r"(r2), "=r"(r3) : "r"(addr));
}
__device__ __forceinline__ void redv2(float* p, float a, float b) {
    asm volatile("red.global.add.v2.f32 [%0], {%1,%2};" :: "l"(p), "f"(a), "f"(b) : "memory");
}
__device__ __forceinline__ float warpsum(float v) {
#pragma unroll
    for (int o = 16; o; o >>= 1) v += __shfl_xor_sync(0xffffffffu, v, o);
    return v;
}
__device__ __forceinline__ float4 ldh4(const __half* p) {
    const __half2* q = (const __half2*)p;
    float2 a = __half22float2(q[0]);
    float2 b = __half22float2(q[1]);
    return make_float4(a.x, a.y, b.x, b.y);
}

// ---------------- weight convert to fp16 ------------------------------------
__global__ void round_all(const float* i0, __half* o0, int n0,
                          const float* i1, __half* o1, int n1,
                          const float* i2, __half* o2, int n2,
                          const float* i3, __half* o3, int n3)
{
    int stride = gridDim.x * blockDim.x;
    for (int i = blockIdx.x * blockDim.x + threadIdx.x; i < n0; i += stride)
        o0[i] = __float2half_rn(i0[i]);
    for (int i = blockIdx.x * blockDim.x + threadIdx.x; i < n1; i += stride)
        o1[i] = __float2half_rn(i1[i]);
    for (int i = blockIdx.x * blockDim.x + threadIdx.x; i < n2; i += stride)
        o2[i] = __float2half_rn(i2[i]);
    for (int i = blockIdx.x * blockDim.x + threadIdx.x; i < n3; i += stride)
        o3[i] = __float2half_rn(i3[i]);
}

__global__ void tohalf(const float* __restrict__ in, __half* __restrict__ out, int n)
{
    int i = blockIdx.x * blockDim.x + threadIdx.x;
    if (i < n) out[i] = __float2half_rn(in[i]);
}

// ---------------- wal = W^T al, war = W^T ar ---------------------------------
__global__ void walprep(const float* __restrict__ W, const float* __restrict__ al,
                        const float* __restrict__ ar,
                        float* __restrict__ wal, float* __restrict__ war)
{
    int h = blockIdx.x, g = blockIdx.y, k = threadIdx.x;
    float sl = 0.f, sr = 0.f;
    const float* wb = W + ((size_t)g * HD + h * DD) * DD + k;
    const float* alb = al + (g * HH + h) * DD;
    const float* arb = ar + (g * HH + h) * DD;
    for (int d = 0; d < DD; d++) {
        float wv = wb[(size_t)d * DD];
        sl += wv * alb[d];
        sr += wv * arb[d];
    }
    wal[(g * HH + h) * DD + k] = sl;
    war[(g * HH + h) * DD + k] = sr;
}

// ---------------- fused per-layer prep (reads fp16 feat) ---------------------
__global__ void prep_kernel(const __half* __restrict__ feat16,
                            const float* __restrict__ walL, const float* __restrict__ warL,
                            float* __restrict__ elb, float* __restrict__ erb,
                            const int* __restrict__ edge_dst,
                            const float* __restrict__ relWc, const float* __restrict__ relbc,
                            float* __restrict__ coef,
                            const float* __restrict__ nodeWc, const float* __restrict__ nodebc,
                            float* __restrict__ ncoef)
{
    int w = (blockIdx.x * blockDim.x + threadIdx.x) >> 5;
    int lane = threadIdx.x & 31;
    if (w < 2 * 2 * N_USER) {
        int side = w / (2 * N_USER);
        int u = w - side * 2 * N_USER;
        int isEr = u >= N_USER;
        int i = u - (isEr ? N_USER : 0);
        int n = (side == 0) ? (isEr ? i : N_USER + i) : (isEr ? N_USER + i : i);
        float4 f = ldh4(feat16 + (long long)n * DD + lane * 4);
        const float* wb = (isEr ? warL : walL) + side * HH * DD;
        float* ob = (isEr ? erb : elb) + side * N_USER * HH + i * HH;
#pragma unroll
        for (int h = 0; h < HH; h++) {
            float4 a = ((const float4*)(wb + h * DD))[lane];
            float s = f.x * a.x + f.y * a.y + f.z * a.z + f.w * a.w;
#pragma unroll
            for (int o = 16; o; o >>= 1) s += __shfl_down_sync(0xffffffffu, s, o);
            if (lane == 0) ob[h] = s;
        }
    } else if (w < 2 * 2 * N_USER + TT * E_T_) {
        int warp = w - 2 * 2 * N_USER;
        int t = warp / E_T_;
        int d = edge_dst[warp];
        float4 hv = ldh4(feat16 + (long long)d * DD + lane * 4);
#pragma unroll
        for (int m = 0; m < MM; m++) {
            float4 ww = ((const float4*)(relWc + ((long long)t * MM + m) * DD))[lane];
            float s = hv.x * ww.x + hv.y * ww.y + hv.z * ww.z + hv.w * ww.w;
#pragma unroll
            for (int o = 16; o; o >>= 1) s += __shfl_down_sync(0xffffffffu, s, o);
            if (lane == 0) coef[(long long)warp * MM + m] = lrelu(s + relbc[t * MM + m]);
        }
    } else if (w < 2 * 2 * N_USER + TT * E_T_ + NTOT) {
        int warp = w - (2 * 2 * N_USER + TT * E_T_);
        float4 hv = ldh4(feat16 + (long long)warp * DD + lane * 4);
#pragma unroll
        for (int m = 0; m < MM; m++) {
            float4 ww = ((const float4*)(nodeWc + (long long)m * DD))[lane];
            float s = hv.x * ww.x + hv.y * ww.y + hv.z * ww.z + hv.w * ww.w;
#pragma unroll
            for (int o = 16; o; o >>= 1) s += __shfl_down_sync(0xffffffffu, s, o);
            if (lane == 0) ncoef[(long long)warp * MM + m] = lrelu(s + nodebc[m]);
        }
    }
}
#define PREP_WARPS (2 * 2 * N_USER + TT * E_T_ + NTOT)   // 200000

// ---------------- CSR build --------------------------------------------------
__global__ void hist_kernel(const int* __restrict__ dst, int* __restrict__ deg, int n)
{
    int i = blockIdx.x * blockDim.x + threadIdx.x;
    if (i < n) atomicAdd(&deg[dst[i]], 1);
}

__global__ void scan_fast(const int* __restrict__ deg, int* __restrict__ off, int n)
{
    __shared__ int wsum[32];
    int tid  = threadIdx.x;
    int lane = tid & 31, w = tid >> 5;
    int C = (n + 1023) >> 10;
    int start = tid * C;
    int end = min(start + C, n);
    int total = 0;
    for (int i = start; i < end; i++) total += deg[i];
    int incl = total;
#pragma unroll
    for (int o = 1; o < 32; o <<= 1) {
        int v = __shfl_up_sync(0xffffffffu, incl, o);
        if (lane >= o) incl += v;
    }
    if (lane == 31) wsum[w] = incl;
    __syncthreads();
    if (w == 0) {
        int v = wsum[lane];
        int iv = v;
#pragma unroll
        for (int o = 1; o < 32; o <<= 1) {
            int u = __shfl_up_sync(0xffffffffu, iv, o);
            if (lane >= o) iv += u;
        }
        wsum[lane] = iv - v;
    }
    __syncthreads();
    int run = wsum[w] + incl - total;
    for (int i = start; i < end; i++) {
        run += deg[i];
        off[i + 1] = run;
    }
    if (tid == 0) off[0] = 0;
}

__global__ void fill_csr(const int* __restrict__ dst, int* __restrict__ cur,
                         int* __restrict__ eid, int n)
{
    int i = blockIdx.x * blockDim.x + threadIdx.x;
    if (i < n) {
        int pos = atomicAdd(&cur[dst[i]], 1);
        eid[pos] = i;
    }
}

// ---------------- fp16 tensor-core GEMM (BK=64, ldmatrix, dual-cfg, splitK) --
#define BK 64
#define LDT 72
#define TILEH (128 * LDT)
#define SMB (2 * 2 * TILEH * 2 + 1024 * 4)

struct GemmCfg {
    const __half* A; const int* gidx; const float* coef;
    const __half* B; int bSeg; long long bStride; long long bTStride;
    float* C; __half* Ch; const int* sidx; const float* bias; int biasTS; int act;
    int aOff0, aOff1; long long cTStride;
    int Mrows, K, aSeg, ldc, tilesPerT, kSplit;
};

__global__ __launch_bounds__(256, 2)
void gemm_fp16(GemmCfg c0, GemmCfg c1, int splitY)
{
    const bool first = (int)blockIdx.y < splitY;
    const GemmCfg c = first ? c0 : c1;
    const int by = first ? blockIdx.y : blockIdx.y - splitY;

    extern __shared__ __half smh[];
    float* sCoef = (float*)(smh + 4 * TILEH);

    const int tid  = threadIdx.x;
    const int lane = tid & 31, wid = tid >> 5;
    const int warpM = wid & 3, warpN = wid >> 2;
    const int t    = by / c.tilesPerT;
    const int row0 = (by % c.tilesPerT) * 128;
    const bool ksp = c.kSplit > 1;
    const int kLen = c.K / c.kSplit;
    const int kBase = ksp ? (int)blockIdx.x * kLen : 0;
    const int col0 = ksp ? 0 : blockIdx.x * 128;
    const int aOff = t ? c.aOff1 : c.aOff0;

    const int lrow = tid >> 1;
    const int lcol = (tid & 1) * 32;
    const int growL  = row0 + lrow;
    const bool rowokL = growL < c.Mrows;
    const int arowL  = (rowokL ? (c.gidx ? c.gidx[(long long)t * c.Mrows + growL] : growL) : 0) + aOff;
    const __half* AbaseL = c.A + (long long)arowL * c.aSeg + lcol;
    const __half* BbaseL = c.B + t * c.bTStride + (long long)(col0 + lrow) * c.bSeg + lcol;
    const int aBytes = rowokL ? 16 : 0;

    if (c.coef) {
        for (int i = tid; i < 1024; i += 256) {
            int r = i >> 3, m = i & 7;
            int gr = row0 + r;
            sCoef[i] = (gr < c.Mrows) ? c.coef[((long long)t * c.Mrows + gr) * 8 + m] : 0.f;
        }
    }

    const unsigned smBase = (unsigned)__cvta_generic_to_shared(smh);
    unsigned aoffB[2];
#pragma unroll
    for (int mt = 0; mt < 2; mt++) {
        int ar = warpM * 32 + mt * 16 + (lane & 15);
        int ak = (lane >> 4) << 3;
        aoffB[mt] = (unsigned)(ar * LDT + ak) * 2;
    }
    unsigned boffB[4];
#pragma unroll
    for (int p = 0; p < 4; p++) {
        int nr = warpN * 64 + (p * 2 + (lane >> 4)) * 8 + (lane & 7);
        int nk = ((lane >> 3) & 1) << 3;
        boffB[p] = (unsigned)(nr * LDT + nk) * 2 + (unsigned)TILEH * 2;
    }

    float acc[2][8][4];
#pragma unroll
    for (int i = 0; i < 2; i++)
#pragma unroll
        for (int j = 0; j < 8; j++)
#pragma unroll
            for (int q = 0; q < 4; q++) acc[i][j][q] = 0.f;

    const int ntiles = kLen / BK;

    auto loadTile = [&](int kt, int b) {
        int kg = kBase + kt * BK;
        const __half* ga = AbaseL + kg % c.aSeg;
        const __half* gb = BbaseL + (long long)(kg / c.bSeg) * c.bStride + kg % c.bSeg;
        unsigned da = (unsigned)__cvta_generic_to_shared(smh + b * 2 * TILEH + lrow * LDT + lcol);
        unsigned db = (unsigned)__cvta_generic_to_shared(smh + b * 2 * TILEH + TILEH + lrow * LDT + lcol);
#pragma unroll
        for (int j = 0; j < 4; j++) {
            asm volatile("cp.async.ca.shared.global [%0], [%1], 16, %2;"
                         :: "r"(da + j * 16), "l"(ga + j * 8), "r"(aBytes));
            asm volatile("cp.async.ca.shared.global [%0], [%1], 16;"
                         :: "r"(db + j * 16), "l"(gb + j * 8));
        }
    };

    loadTile(0, 0);
    asm volatile("cp.async.commit_group;");
    int buf = 0;
    for (int kt = 0; kt < ntiles; kt++) {
        asm volatile("cp.async.wait_group 0;");
        __syncthreads();
        if (kt + 1 < ntiles) {
            loadTile(kt + 1, buf ^ 1);
            asm volatile("cp.async.commit_group;");
        }

        const unsigned tileB = smBase + (unsigned)(buf * 2 * TILEH) * 2;
        __half2 cf2[2][2];
        if (c.coef) {
            int seg = (kBase + kt * BK) / c.aSeg;
#pragma unroll
            for (int mt = 0; mt < 2; mt++) {
                int rr = warpM * 32 + mt * 16 + (lane >> 2);
                cf2[mt][0] = __float2half2_rn(sCoef[rr * 8 + seg]);
                cf2[mt][1] = __float2half2_rn(sCoef[(rr + 8) * 8 + seg]);
            }
        }
#pragma unroll
        for (int kk = 0; kk < BK; kk += 16) {
            unsigned af[2][4], bf[8][2];
#pragma unroll
            for (int mt = 0; mt < 2; mt++) {
                ldsm4(af[mt][0], af[mt][1], af[mt][2], af[mt][3],
                      tileB + aoffB[mt] + kk * 2);
                if (c.coef) {
                    __half2* a2 = (__half2*)af[mt];
                    a2[0] = __hmul2(a2[0], cf2[mt][0]);
                    a2[1] = __hmul2(a2[1], cf2[mt][1]);
                    a2[2] = __hmul2(a2[2], cf2[mt][0]);
                    a2[3] = __hmul2(a2[3], cf2[mt][1]);
                }
            }
#pragma unroll
            for (int p = 0; p < 4; p++) {
                ldsm4(bf[2 * p][0], bf[2 * p][1], bf[2 * p + 1][0], bf[2 * p + 1][1],
                      tileB + boffB[p] + kk * 2);
            }
#pragma unroll
            for (int mt = 0; mt < 2; mt++)
#pragma unroll
                for (int nt = 0; nt < 8; nt++)
                    mma16816(acc[mt][nt], af[mt], bf[nt]);
        }
        buf ^= 1;
    }

    // epilogue
#pragma unroll
    for (int mt = 0; mt < 2; mt++)
#pragma unroll
        for (int h = 0; h < 2; h++) {
            int r = row0 + warpM * 32 + mt * 16 + (lane >> 2) + 8 * h;
            if (r >= c.Mrows) continue;
            if (c.sidx) {
                long long orow = c.sidx[(long long)t * c.Mrows + r];
                long long base = orow * c.ldc + col0;
#pragma unroll
                for (int nt = 0; nt < 8; nt++) {
                    int cc = warpN * 64 + nt * 8 + 2 * (lane & 3);
                    redv2(&c.C[base + cc], acc[mt][nt][2 * h], acc[mt][nt][2 * h + 1]);
                }
            } else if (ksp) {
                long long base = (long long)t * c.cTStride + (long long)r * c.ldc + col0;
#pragma unroll
                for (int nt = 0; nt < 8; nt++) {
                    int cc = warpN * 64 + nt * 8 + 2 * (lane & 3);
                    redv2(&c.C[base + cc], acc[mt][nt][2 * h], acc[mt][nt][2 * h + 1]);
                }
            } else {
                long long base = (long long)t * c.cTStride + (long long)r * c.ldc + col0;
#pragma unroll
                for (int nt = 0; nt < 8; nt++) {
                    int cc = warpN * 64 + nt * 8 + 2 * (lane & 3);
                    float v0 = acc[mt][nt][2 * h];
                    float v1 = acc[mt][nt][2 * h + 1];
                    if (c.bias) {
                        v0 += c.bias[t * c.biasTS + col0 + cc];
                        v1 += c.bias[t * c.biasTS + col0 + cc + 1];
                    }
                    if (c.act == 1) { v0 = eluf(v0); v1 = eluf(v1); }
                    if (c.Ch) {
                        *(__half2*)&c.Ch[base + cc] = __floats2half2_rn(v0, v1);
                    } else {
                        float2 v = make_float2(v0, v1);
                        *(float2*)&c.C[base + cc] = v;
                    }
                }
            }
        }
}

// ---------------- fused CSR GAT (both sides, one launch; fp16 fc gather) -----
__global__ void gat_agg2(const int* __restrict__ off_u, const int* __restrict__ eid_u,
                         const int* __restrict__ off_i, const int* __restrict__ eid_i,
                         const int* __restrict__ dst_i, const int* __restrict__ src_u,
                         const float* __restrict__ elb, const float* __restrict__ erb,
                         const __half* __restrict__ fcb, const float* __restrict__ biasb,
                         __half* __restrict__ rstb)
{
    int w = (blockIdx.x * blockDim.x + threadIdx.x) >> 5;
    int lane = threadIdx.x & 31;
    if (w >= 2 * N_USER * HH) return;
    int side = w >= N_USER * HH;
    int wl = w - side * N_USER * HH;
    int node = wl >> 2, h = wl & 3;
    const int* off  = side ? off_i : off_u;
    const int* eid  = side ? eid_i : eid_u;
    const int* sIdx = side ? src_u : dst_i;
    const float* el = elb + side * N_USER * HH;
    float erd = (erb + side * N_USER * HH)[node * HH + h];
    const __half* fc = fcb + (size_t)side * N_USER * HD;
    const float* bias = biasb + side * HD;
    __half* rst = rstb + (size_t)side * N_USER * HD;

    int o0 = off[node], o1 = off[node + 1];

    float m = -1e30f;
    for (int j = o0 + lane; j < o1; j += 32) {
        int s = sIdx[eid[j]];
        m = fmaxf(m, lrelu(el[s * HH + h] + erd));
    }
#pragma unroll
    for (int o = 16; o; o >>= 1) m = fmaxf(m, __shfl_xor_sync(0xffffffffu, m, o));

    float4 acc = make_float4(0.f, 0.f, 0.f, 0.f);
    float den = 0.f;
    for (int j = o0; j < o1; j++) {
        int s = sIdx[eid[j]];
        float ex = expf(lrelu(el[s * HH + h] + erd) - m);
        den += ex;
        const __half2* fp = (const __half2*)(fc + (long long)s * HD + h * DD + lane * 4);
        float2 fa = __half22float2(fp[0]);
        float2 fb = __half22float2(fp[1]);
        acc.x += ex * fa.x; acc.y += ex * fa.y; acc.z += ex * fb.x; acc.w += ex * fb.y;
    }
    float inv = (o1 > o0) ? 1.f / den : 0.f;
    float4 b = ((const float4*)(bias + h * DD))[lane];
    __half2 h0 = __floats2half2_rn(eluf(acc.x * inv + b.x), eluf(acc.y * inv + b.y));
    __half2 h1 = __floats2half2_rn(eluf(acc.z * inv + b.z), eluf(acc.w * inv + b.w));
    __half2* dst = (__half2*)(rst + (long long)node * HD + h * DD + lane * 4);
    dst[0] = h0; dst[1] = h1;
}

__global__ void cnt_kernel(const int* __restrict__ edge_dst, float* __restrict__ cnt)
{
    int i = blockIdx.x * blockDim.x + threadIdx.x;
    if (i >= TT * E_T_) return;
    atomicAdd(&cnt[edge_dst[i]], 1.f);
}

// ---------------- combine (warp per node; proj bias+elu folded in) -----------
__global__ void combine_kernel(const float* __restrict__ s, const float* __restrict__ cnt,
                               const float* __restrict__ lnw, const float* __restrict__ lnb,
                               const float* __restrict__ hbias,
                               const float* __restrict__ node, const float* __restrict__ trans,
                               const float* __restrict__ projb,
                               __half* __restrict__ featOut16,
                               float* __restrict__ embOut)
{
    int w = (blockIdx.x * blockDim.x + threadIdx.x) >> 5;
    int lane = threadIdx.x & 31;
    if (w >= NTOT) return;
    int n = w;
    float inv = 1.f / fmaxf(cnt[n], 1.f);
    float4 sv = ((const float4*)(s + (long long)n * DD))[lane];
    float4 agg = make_float4(sv.x * inv, sv.y * inv, sv.z * inv, sv.w * inv);
    float mean = warpsum(agg.x + agg.y + agg.z + agg.w) * (1.f / DD);
    float4 df = make_float4(agg.x - mean, agg.y - mean, agg.z - mean, agg.w - mean);
    float var = warpsum(df.x * df.x + df.y * df.y + df.z * df.z + df.w * df.w) * (1.f / DD);
    float rs = rsqrtf(var + 1e-5f);
    float4 wv = ((const float4*)lnw)[lane];
    float4 bv = ((const float4*)lnb)[lane];
    float4 hv = ((const float4*)hbias)[lane];
    float4 nv = ((const float4*)(node + (long long)n * DD))[lane];
    float4 tv = ((const float4*)(trans + (long long)n * DD))[lane];
    int side = n >= N_USER;
    float4 pb = ((const float4*)(projb + side * DD))[lane];
    float4 f;
    f.x = lrelu(df.x * rs * wv.x + bv.x + hv.x + nv.x) + eluf(tv.x + pb.x);
    f.y = lrelu(df.y * rs * wv.y + bv.y + hv.y + nv.y) + eluf(tv.y + pb.y);
    f.z = lrelu(df.z * rs * wv.z + bv.z + hv.z + nv.z) + eluf(tv.z + pb.z);
    f.w = lrelu(df.w * rs * wv.w + bv.w + hv.w + nv.w) + eluf(tv.w + pb.w);
    __half2* f16 = (__half2*)(featOut16 + (long long)n * DD + lane * 4);
    f16[0] = __floats2half2_rn(f.x, f.y);
    f16[1] = __floats2half2_rn(f.z, f.w);
    ((float4*)(embOut + (long long)n * DD))[lane] = f;
}

// ---------------- final layernorm (warp per node) ----------------------------
__global__ void final_kernel(const float* __restrict__ emb0,
                             const float* __restrict__ e1, const float* __restrict__ e2,
                             const float* __restrict__ w, const float* __restrict__ b,
                             float* __restrict__ out)
{
    int wp = (blockIdx.x * blockDim.x + threadIdx.x) >> 5;
    int lane = threadIdx.x & 31;
    if (wp >= NTOT) return;
    int n = wp;
    float4 x0 = ((const float4*)(emb0 + (long long)n * DD))[lane];
    float4 x1 = ((const float4*)(e1 + (long long)n * DD))[lane];
    float4 x2 = ((const float4*)(e2 + (long long)n * DD))[lane];
    float mean = warpsum(x0.x + x0.y + x0.z + x0.w + x1.x + x1.y + x1.z + x1.w
                       + x2.x + x2.y + x2.z + x2.w) * (1.f / 384.f);
    float4 d0 = make_float4(x0.x - mean, x0.y - mean, x0.z - mean, x0.w - mean);
    float4 d1 = make_float4(x1.x - mean, x1.y - mean, x1.z - mean, x1.w - mean);
    float4 d2 = make_float4(x2.x - mean, x2.y - mean, x2.z - mean, x2.w - mean);
    float var = warpsum(d0.x * d0.x + d0.y * d0.y + d0.z * d0.z + d0.w * d0.w
                      + d1.x * d1.x + d1.y * d1.y + d1.z * d1.z + d1.w * d1.w
                      + d2.x * d2.x + d2.y * d2.y + d2.z * d2.z + d2.w * d2.w) * (1.f / 384.f);
    float rs = rsqrtf(var + 1e-5f);
    long long base = (long long)n * 384;
    float4 w0 = ((const float4*)w)[lane];
    float4 w1 = ((const float4*)(w + 128))[lane];
    float4 w2 = ((const float4*)(w + 256))[lane];
    float4 b0 = ((const float4*)b)[lane];
    float4 b1 = ((const float4*)(b + 128))[lane];
    float4 b2 = ((const float4*)(b + 256))[lane];
    float4 o0 = make_float4(d0.x * rs * w0.x + b0.x, d0.y * rs * w0.y + b0.y,
                            d0.z * rs * w0.z + b0.z, d0.w * rs * w0.w + b0.w);
    float4 o1 = make_float4(d1.x * rs * w1.x + b1.x, d1.y * rs * w1.y + b1.y,
                            d1.z * rs * w1.z + b1.z, d1.w * rs * w1.w + b1.w);
    float4 o2 = make_float4(d2.x * rs * w2.x + b2.x, d2.y * rs * w2.y + b2.y,
                            d2.z * rs * w2.z + b2.z, d2.w * rs * w2.w + b2.w);
    ((float4*)(out + base))[lane]       = o0;
    ((float4*)(out + base + 128))[lane] = o1;
    ((float4*)(out + base + 256))[lane] = o2;
}

// ---------------- host driver ------------------------------------------------
extern "C" void kernel_launch(void* const* d_in, const int* in_sizes, int n_in,
                              void* d_out, int out_size)
{
    const float* embedding = (const float*)d_in[0];
    const float* gat_fc_W  = (const float*)d_in[1];
    const float* gat_al    = (const float*)d_in[2];
    const float* gat_ar    = (const float*)d_in[3];
    const float* gat_bias  = (const float*)d_in[4];
    const float* proj_W    = (const float*)d_in[5];
    const float* proj_b    = (const float*)d_in[6];
    const float* rel_Wc    = (const float*)d_in[7];
    const float* rel_bc    = (const float*)d_in[8];
    const float* rel_Ww    = (const float*)d_in[9];
    const float* node_Wc   = (const float*)d_in[10];
    const float* node_bc   = (const float*)d_in[11];
    const float* node_Ww   = (const float*)d_in[12];
    const float* h_bias    = (const float*)d_in[13];
    const float* ln_w      = (const float*)d_in[14];
    const float* ln_b      = (const float*)d_in[15];
    const float* fln_w     = (const float*)d_in[16];
    const float* fln_b     = (const float*)d_in[17];
    const int*   src_u     = (const int*)d_in[18];
    const int*   dst_i     = (const int*)d_in[19];
    const int*   edge_src  = (const int*)d_in[20];
    const int*   edge_dst  = (const int*)d_in[21];
    float* out = (float*)d_out;

    float *p_el, *p_er, *p_trans, *p_coef,
          *p_ncoef, *p_s, *p_cnt, *p_node, *p_e1, *p_e2,
          *p_wal, *p_war;
    __half *p_fc16, *p_feat16, *p_rst16, *p_wfc, *p_wproj, *p_wrel, *p_wnode;
    int *p_off_u, *p_off_i, *p_eid_u, *p_eid_i, *p_deg, *p_cur;
    cudaGetSymbolAddress((void**)&p_fc16, g_fc16);
    cudaGetSymbolAddress((void**)&p_rst16, g_rst16);
    cudaGetSymbolAddress((void**)&p_el, g_el);
    cudaGetSymbolAddress((void**)&p_er, g_er);
    cudaGetSymbolAddress((void**)&p_trans, g_trans);
    cudaGetSymbolAddress((void**)&p_coef, g_coef);
    cudaGetSymbolAddress((void**)&p_ncoef, g_ncoef);
    cudaGetSymbolAddress((void**)&p_s, g_s);
    cudaGetSymbolAddress((void**)&p_cnt, g_cnt);
    cudaGetSymbolAddress((void**)&p_node, g_node);
    cudaGetSymbolAddress((void**)&p_feat16, g_feat16);
    cudaGetSymbolAddress((void**)&p_e1, g_emb1);
    cudaGetSymbolAddress((void**)&p_e2, g_emb2);
    cudaGetSymbolAddress((void**)&p_wfc, g_wfc);
    cudaGetSymbolAddress((void**)&p_wproj, g_wproj);
    cudaGetSymbolAddress((void**)&p_wrel, g_wrel);
    cudaGetSymbolAddress((void**)&p_wnode, g_wnode);
    cudaGetSymbolAddress((void**)&p_wal, g_wal);
    cudaGetSymbolAddress((void**)&p_war, g_war);
    cudaGetSymbolAddress((void**)&p_off_u, g_off_u);
    cudaGetSymbolAddress((void**)&p_off_i, g_off_i);
    cudaGetSymbolAddress((void**)&p_eid_u, g_eid_u);
    cudaGetSymbolAddress((void**)&p_eid_i, g_eid_i);
    cudaGetSymbolAddress((void**)&p_deg, g_deg);
    cudaGetSymbolAddress((void**)&p_cur, g_cur);

    cudaFuncSetAttribute(gemm_fp16, cudaFuncAttributeMaxDynamicSharedMemorySize, SMB);

    auto mkCfg = [](const __half* A, const int* gidx, const float* coefp,
                    const __half* B, int bSeg, long long bStride, long long bTStride,
                    float* C, __half* Ch, const int* sidx,
                    const float* bias, int biasTS, int act,
                    int aOff0, int aOff1, long long cTStride,
                    int M, int K, int aSeg, int ldc, int tilesPerT, int kSplit) {
        GemmCfg c;
        c.A = A; c.gidx = gidx; c.coef = coefp;
        c.B = B; c.bSeg = bSeg; c.bStride = bStride; c.bTStride = bTStride;
        c.C = C; c.Ch = Ch; c.sidx = sidx; c.bias = bias; c.biasTS = biasTS; c.act = act;
        c.aOff0 = aOff0; c.aOff1 = aOff1; c.cTStride = cTStride;
        c.Mrows = M; c.K = K; c.aSeg = aSeg; c.ldc = ldc; c.tilesPerT = tilesPerT;
        c.kSplit = kSplit;
        return c;
    };

    // ---- side stream + events (per call; capture-safe; leaked) ----
    cudaStream_t sB;
    cudaStreamCreateWithFlags(&sB, cudaStreamNonBlocking);
    cudaEvent_t eFork, eCSR, eComb[2], ePrep[2], eMem[2];
    cudaEventCreateWithFlags(&eFork, cudaEventDisableTiming);
    cudaEventCreateWithFlags(&eCSR,  cudaEventDisableTiming);
    for (int l = 0; l < 2; l++) {
        cudaEventCreateWithFlags(&eComb[l], cudaEventDisableTiming);
        cudaEventCreateWithFlags(&ePrep[l], cudaEventDisableTiming);
        cudaEventCreateWithFlags(&eMem[l],  cudaEventDisableTiming);
    }

    cudaEventRecord(eFork, 0);
    cudaStreamWaitEvent(sB, eFork, 0);

    cudaMemsetAsync(p_cnt, 0, NTOT * 4, sB);
    cnt_kernel<<<(TT * E_T_ + 255) / 256, 256, 0, sB>>>(edge_dst, p_cnt);
    cudaMemsetAsync(p_deg, 0, N_USER * 4, sB);
    hist_kernel<<<(E_UI_ + 255) / 256, 256, 0, sB>>>(src_u, p_deg, E_UI_);
    scan_fast<<<1, 1024, 0, sB>>>(p_deg, p_off_u, N_USER);
    cudaMemcpyAsync(p_cur, p_off_u, N_USER * 4, cudaMemcpyDeviceToDevice, sB);
    fill_csr<<<(E_UI_ + 255) / 256, 256, 0, sB>>>(src_u, p_cur, p_eid_u, E_UI_);
    cudaMemsetAsync(p_deg, 0, N_ITEM * 4, sB);
    hist_kernel<<<(E_UI_ + 255) / 256, 256, 0, sB>>>(dst_i, p_deg, E_UI_);
    scan_fast<<<1, 1024, 0, sB>>>(p_deg, p_off_i, N_ITEM);
    cudaMemcpyAsync(p_cur, p_off_i, N_ITEM * 4, cudaMemcpyDeviceToDevice, sB);
    fill_csr<<<(E_UI_ + 255) / 256, 256, 0, sB>>>(dst_i, p_cur, p_eid_i, E_UI_);
    cudaEventRecord(eCSR, sB);

    round_all<<<512, 256>>>(gat_fc_W, p_wfc, 2*2*HD*DD,
                            proj_W, p_wproj, 2*2*DD*HD,
                            rel_Ww, p_wrel, 2*TT*MM*DD*DD,
                            node_Ww, p_wnode, 2*MM*DD*DD);
    walprep<<<dim3(HH, 4), DD>>>(gat_fc_W, gat_al, gat_ar, p_wal, p_war);
    tohalf<<<(NTOT * DD + 255) / 256, 256>>>(embedding, p_feat16, NTOT * DD);
    cudaEventRecord(eComb[0], 0);

    for (int l = 0; l < 2; l++) {
        // side chain: prep -> memset s -> rel + node (fully fused) gemm
        cudaStreamWaitEvent(sB, eComb[l], 0);
        prep_kernel<<<(PREP_WARPS * 32 + 255) / 256, 256, 0, sB>>>(
            p_feat16, p_wal + (size_t)l * 2 * HH * DD, p_war + (size_t)l * 2 * HH * DD,
            p_el, p_er,
            edge_dst, rel_Wc + (size_t)l * TT * MM * DD, rel_bc + (size_t)l * TT * MM, p_coef,
            node_Wc + (size_t)l * MM * DD, node_bc + (size_t)l * MM, p_ncoef);
        cudaEventRecord(ePrep[l], sB);
        cudaMemsetAsync(p_s, 0, (size_t)NTOT * DD * 4, sB);
        {
            GemmCfg cr = mkCfg(p_feat16, edge_src, p_coef,
                               p_wrel + (size_t)l * TT * MM * DD * DD, DD,
                               (long long)DD * DD, (long long)MM * DD * DD,
                               p_s, nullptr, edge_dst, nullptr, 0, 0,
                               0, 0, 0,
                               E_T_, MM * DD, DD, DD, 125, 1);
            GemmCfg cn = mkCfg(p_feat16, nullptr, p_ncoef,
                               p_wnode + (size_t)l * MM * DD * DD, DD,
                               (long long)DD * DD, 0,
                               p_node, nullptr, nullptr, nullptr, 0, 0,
                               0, 0, 0,
                               NTOT, MM * DD, DD, DD, 313, 1);
            int splitY = TT * 125;
            dim3 g(1, splitY + 313);
            gemm_fp16<<<g, 256, SMB, sB>>>(cr, cn, splitY);
        }
        cudaEventRecord(eMem[l], sB);

        // main chain: fc gemm -> gat -> proj(splitK)
        {
            GemmCfg cf = mkCfg(p_feat16, nullptr, nullptr,
                               p_wfc + (size_t)l * 2 * HD * DD, DD, 0, (long long)HD * DD,
                               nullptr, p_fc16, nullptr, nullptr, 0, 0,
                               N_USER, 0, (long long)N_USER * HD,
                               N_USER, DD, DD, HD, 157, 1);
            dim3 g(HD / 128, 157 * 2);
            gemm_fp16<<<g, 256, SMB>>>(cf, cf, 1 << 30);
        }
        cudaMemsetAsync(p_trans, 0, (size_t)NTOT * DD * 4);
        if (l == 0) cudaStreamWaitEvent(0, eCSR, 0);
        cudaStreamWaitEvent(0, ePrep[l], 0);
        gat_agg2<<<(2 * N_USER * HH * 32 + 255) / 256, 256>>>(
            p_off_u, p_eid_u, p_off_i, p_eid_i, dst_i, src_u,
            p_el, p_er, p_fc16, gat_bias + (size_t)l * 2 * HD, p_rst16);
        {
            GemmCfg cp = mkCfg(p_rst16, nullptr, nullptr,
                               p_wproj + (size_t)l * 2 * DD * HD, HD, 0, (long long)DD * HD,
                               p_trans, nullptr, nullptr,
                               nullptr, 0, 0,
                               0, N_USER, (long long)N_USER * DD,
                               N_USER, HD, HD, DD, 157, 2);
            dim3 g(2, 157 * 2);
            gemm_fp16<<<g, 256, SMB>>>(cp, cp, 1 << 30);
        }

        cudaStreamWaitEvent(0, eMem[l], 0);
        combine_kernel<<<(NTOT * 32 + 255) / 256, 256>>>(
            p_s, p_cnt, ln_w + (size_t)l * DD, ln_b + (size_t)l * DD,
            h_bias + (size_t)l * DD, p_node, p_trans,
            proj_b + (size_t)l * 2 * DD,
            p_feat16, l == 0 ? p_e1 : p_e2);
        if (l == 0) cudaEventRecord(eComb[1], 0);
    }
    final_kernel<<<(NTOT * 32 + 255) / 256, 256>>>(embedding, p_e1, p_e2, fln_w, fln_b, out);
    (void)in_sizes; (void)n_in; (void)out_size;
}